// round 2
// baseline (speedup 1.0000x reference)
#include <cuda_runtime.h>
#include <math.h>

#define BATCH 2
#define SEQ   4096
#define EMBED 768
#define NHEAD 8
#define HDIM  96
#define MTOT  (BATCH*SEQ)          // 8192
#define QKV_N (3*EMBED)            // 2304
#define SCALE_F 0.10206207261596575f  // 96^-0.5

// Scratch (allocations are forbidden; __device__ globals are the sanctioned path)
__device__ float g_q[(size_t)BATCH*NHEAD*SEQ*HDIM];   // [B,H,N,D]
__device__ float g_k[(size_t)BATCH*NHEAD*SEQ*HDIM];
__device__ float g_v[(size_t)BATCH*NHEAD*SEQ*HDIM];
__device__ float g_att[(size_t)MTOT*EMBED];           // [B*N, C] attention output

// ---------------------------------------------------------------------------
// C = A @ B^T   (A: [M,K] row-major, B: [N,K] row-major — both layers store
// weights [out,in] so this covers QKV and proj).
// 128x128 block tile, K-tile 8, 8x8 per-thread microtile, 256 threads.
// MODE 0: A = x, scatter output into g_q/g_k/g_v per-head layout.
// MODE 1: A = g_att (device global), plain write to C.
// ---------------------------------------------------------------------------
template<int MODE>
__global__ __launch_bounds__(256) void sgemm_abt(const float* __restrict__ A,
                                                 const float* __restrict__ B,
                                                 float* __restrict__ C,
                                                 int M, int N, int K) {
    __shared__ float As[8][132];   // pitch 132 -> conflict-free transposed store
    __shared__ float Bs[8][132];

    const int t  = threadIdx.x;
    const int tx = t & 15;
    const int ty = t >> 4;
    const int m0 = blockIdx.y * 128;
    const int n0 = blockIdx.x * 128;

    const int lrow = t >> 1;        // 0..127
    const int lc4  = (t & 1) * 4;   // 0 or 4

    const float* Ap = (MODE == 1) ? g_att : A;

    float acc[8][8];
#pragma unroll
    for (int i = 0; i < 8; i++)
#pragma unroll
        for (int j = 0; j < 8; j++) acc[i][j] = 0.f;

    const float* aptr = Ap + (size_t)(m0 + lrow) * K + lc4;
    const float* bptr = B  + (size_t)(n0 + lrow) * K + lc4;

    for (int kt = 0; kt < K; kt += 8) {
        float4 av = *(const float4*)(aptr + kt);
        float4 bv = *(const float4*)(bptr + kt);
        __syncthreads();
        As[lc4+0][lrow] = av.x; As[lc4+1][lrow] = av.y;
        As[lc4+2][lrow] = av.z; As[lc4+3][lrow] = av.w;
        Bs[lc4+0][lrow] = bv.x; Bs[lc4+1][lrow] = bv.y;
        Bs[lc4+2][lrow] = bv.z; Bs[lc4+3][lrow] = bv.w;
        __syncthreads();
#pragma unroll
        for (int kk = 0; kk < 8; kk++) {
            float4 a0 = *(const float4*)&As[kk][ty*4];
            float4 a1 = *(const float4*)&As[kk][64 + ty*4];
            float4 b0 = *(const float4*)&Bs[kk][tx*4];
            float4 b1 = *(const float4*)&Bs[kk][64 + tx*4];
            float ar[8] = {a0.x,a0.y,a0.z,a0.w,a1.x,a1.y,a1.z,a1.w};
            float br[8] = {b0.x,b0.y,b0.z,b0.w,b1.x,b1.y,b1.z,b1.w};
#pragma unroll
            for (int i = 0; i < 8; i++)
#pragma unroll
                for (int j = 0; j < 8; j++)
                    acc[i][j] = fmaf(ar[i], br[j], acc[i][j]);
        }
    }

#pragma unroll
    for (int i = 0; i < 8; i++) {
        int mi = m0 + ((i < 4) ? (ty*4 + i) : (64 + ty*4 + (i - 4)));
#pragma unroll
        for (int j = 0; j < 8; j++) {
            int nj = n0 + ((j < 4) ? (tx*4 + j) : (64 + tx*4 + (j - 4)));
            float v = acc[i][j];
            if (MODE == 0) {
                int b = mi >> 12, n = mi & 4095;
                int which = nj / EMBED;          // 0=q, 1=k, 2=v
                int oo = nj - which * EMBED;
                int h = oo / HDIM, d = oo - h * HDIM;
                size_t idx = (((size_t)(b*NHEAD + h))*SEQ + n)*HDIM + d;
                float* dst = (which == 0) ? g_q : (which == 1) ? g_k : g_v;
                dst[idx] = v;
            } else {
                C[(size_t)mi * N + nj] = v;
            }
        }
    }
}

// ---------------------------------------------------------------------------
// Flash attention, fp32. Grid: (SEQ/64, B*H). Block: 256 threads.
// BM=BN=64, D=96. Q/K/V tiles pitch-97 (2-way worst conflicts), S tile pitch-66.
// Writes g_att in [B, N, H*D] layout for the proj GEMM.
// ---------------------------------------------------------------------------
__global__ __launch_bounds__(256) void flash_attn() {
    extern __shared__ float sm[];
    float* Qs   = sm;                 // 64*97
    float* Ks   = Qs + 64*97;         // 64*97
    float* Vs   = Ks + 64*97;         // 64*97
    float* Ss   = Vs + 64*97;         // 64*66
    float* mrow = Ss + 64*66;         // 64
    float* lrow = mrow + 64;          // 64
    float* srow = lrow + 64;          // 64

    const int t  = threadIdx.x;
    const int tx = t & 15;
    const int ty = t >> 4;
    const int bh = blockIdx.y;
    const int q0 = blockIdx.x * 64;

    const float* Qg = g_q + (size_t)bh * SEQ * HDIM;
    const float* Kg = g_k + (size_t)bh * SEQ * HDIM;
    const float* Vg = g_v + (size_t)bh * SEQ * HDIM;

    // Load Q tile (64 rows x 96 floats = 1536 float4)
    for (int i = t; i < 64*24; i += 256) {
        int r = i / 24, c4 = i % 24;
        float4 v = *(const float4*)(Qg + (size_t)(q0 + r) * HDIM + c4*4);
        float* p = &Qs[r*97 + c4*4];
        p[0] = v.x; p[1] = v.y; p[2] = v.z; p[3] = v.w;
    }
    if (t < 64) { mrow[t] = -INFINITY; lrow[t] = 0.f; }

    float acc[4][6];
#pragma unroll
    for (int i = 0; i < 4; i++)
#pragma unroll
        for (int j = 0; j < 6; j++) acc[i][j] = 0.f;

    for (int kt = 0; kt < SEQ/64; kt++) {
        const int k0 = kt * 64;
        __syncthreads();   // previous iteration done using Ks/Vs (and Q ready, iter 0)
        for (int i = t; i < 64*24; i += 256) {
            int r = i / 24, c4 = i % 24;
            float4 kv = *(const float4*)(Kg + (size_t)(k0 + r) * HDIM + c4*4);
            float* pk = &Ks[r*97 + c4*4];
            pk[0] = kv.x; pk[1] = kv.y; pk[2] = kv.z; pk[3] = kv.w;
            float4 vv = *(const float4*)(Vg + (size_t)(k0 + r) * HDIM + c4*4);
            float* pv = &Vs[r*97 + c4*4];
            pv[0] = vv.x; pv[1] = vv.y; pv[2] = vv.z; pv[3] = vv.w;
        }
        __syncthreads();

        // S = Q K^T  (4x4 microtile per thread)
        float s[4][4];
#pragma unroll
        for (int i = 0; i < 4; i++)
#pragma unroll
            for (int j = 0; j < 4; j++) s[i][j] = 0.f;
#pragma unroll 4
        for (int d = 0; d < HDIM; d++) {
            float qv[4], kv[4];
#pragma unroll
            for (int i = 0; i < 4; i++) qv[i] = Qs[(ty*4 + i)*97 + d];
#pragma unroll
            for (int j = 0; j < 4; j++) kv[j] = Ks[(tx*4 + j)*97 + d];
#pragma unroll
            for (int i = 0; i < 4; i++)
#pragma unroll
                for (int j = 0; j < 4; j++)
                    s[i][j] = fmaf(qv[i], kv[j], s[i][j]);
        }
#pragma unroll
        for (int i = 0; i < 4; i++)
#pragma unroll
            for (int j = 0; j < 4; j++)
                Ss[(ty*4 + i)*66 + tx*4 + j] = s[i][j] * SCALE_F;
        __syncthreads();

        // Online softmax per row (threads 0..63 each own one row)
        if (t < 64) {
            float* row = &Ss[t*66];
            float mold = mrow[t];
            float tm = -INFINITY;
#pragma unroll 8
            for (int k = 0; k < 64; k++) tm = fmaxf(tm, row[k]);
            float mn = fmaxf(mold, tm);
            float ts = 0.f;
#pragma unroll 8
            for (int k = 0; k < 64; k++) {
                float p = __expf(row[k] - mn);
                row[k] = p;
                ts += p;
            }
            float sc = __expf(mold - mn);
            lrow[t] = lrow[t] * sc + ts;
            mrow[t] = mn;
            srow[t] = sc;
        }
        __syncthreads();

        // Rescale O, then O += P @ V  (4x6 microtile per thread)
#pragma unroll
        for (int i = 0; i < 4; i++) {
            float sc = srow[ty*4 + i];
#pragma unroll
            for (int j = 0; j < 6; j++) acc[i][j] *= sc;
        }
#pragma unroll 2
        for (int k = 0; k < 64; k++) {
            float pv[4], vv[6];
#pragma unroll
            for (int i = 0; i < 4; i++) pv[i] = Ss[(ty*4 + i)*66 + k];
#pragma unroll
            for (int j = 0; j < 6; j++) vv[j] = Vs[k*97 + tx*6 + j];
#pragma unroll
            for (int i = 0; i < 4; i++)
#pragma unroll
                for (int j = 0; j < 6; j++)
                    acc[i][j] = fmaf(pv[i], vv[j], acc[i][j]);
        }
    }

    // Final normalization + write to [B, N, H*D]
    const int b = bh >> 3, h = bh & 7;
#pragma unroll
    for (int i = 0; i < 4; i++) {
        int q = q0 + ty*4 + i;
        float inv = 1.f / lrow[ty*4 + i];
#pragma unroll
        for (int j = 0; j < 6; j++) {
            int d = tx*6 + j;
            g_att[((size_t)(b*SEQ + q))*EMBED + h*HDIM + d] = acc[i][j] * inv;
        }
    }
}

static const int FLASH_SMEM = (3*64*97 + 64*66 + 3*64) * (int)sizeof(float); // 92160

extern "C" void kernel_launch(void* const* d_in, const int* in_sizes, int n_in,
                              void* d_out, int out_size) {
    const float* x      = (const float*)d_in[0];   // [2,4096,768]
    const float* w_qkv  = (const float*)d_in[1];   // [2304,768]
    const float* w_proj = (const float*)d_in[2];   // [768,768]
    float* out = (float*)d_out;                    // [2,4096,768]

    static bool attr_set = false;
    if (!attr_set) {
        cudaFuncSetAttribute(flash_attn, cudaFuncAttributeMaxDynamicSharedMemorySize,
                             FLASH_SMEM);
        attr_set = true;
    }

    // 1) QKV projection: [8192,768] @ [2304,768]^T -> scatter to g_q/g_k/g_v
    sgemm_abt<0><<<dim3(QKV_N/128, MTOT/128), 256>>>(x, w_qkv, nullptr,
                                                     MTOT, QKV_N, EMBED);
    // 2) Flash attention -> g_att [B,N,C]
    flash_attn<<<dim3(SEQ/64, BATCH*NHEAD), 256, FLASH_SMEM>>>();
    // 3) Output projection: g_att @ w_proj^T -> out
    sgemm_abt<1><<<dim3(EMBED/128, MTOT/128), 256>>>(nullptr, w_proj, out,
                                                     MTOT, EMBED, EMBED);
}

// round 4
// speedup vs baseline: 2.2861x; 2.2861x over previous
#include <cuda_runtime.h>
#include <math.h>
#include <stdint.h>

#define BATCH 2
#define SEQ   4096
#define EMBED 768
#define NHEAD 8
#define HDIM  96
#define MTOT  (BATCH*SEQ)          // 8192
#define QKV_N (3*EMBED)            // 2304
#define SCALE_F 0.10206207261596575f  // 96^-0.5

// Scratch (device globals; allocation is forbidden)
__device__ float g_q[(size_t)BATCH*NHEAD*SEQ*HDIM];   // [B,H,N,D]
__device__ float g_k[(size_t)BATCH*NHEAD*SEQ*HDIM];
__device__ float g_v[(size_t)BATCH*NHEAD*SEQ*HDIM];
__device__ float g_att[(size_t)MTOT*EMBED];           // [B*N, C]

// Round fp32 -> tf32 (rna) once, at smem-store time.
__device__ __forceinline__ float f2tf(float x) {
    uint32_t u;
    asm("cvt.rna.tf32.f32 %0, %1;" : "=r"(u) : "f"(x));
    return __uint_as_float(u);
}

// D = A(16x8,row) * B(8x8,col) + D, tf32 inputs, f32 accum.
__device__ __forceinline__ void mma8(float* c, uint32_t a0, uint32_t a1,
                                     uint32_t a2, uint32_t a3,
                                     uint32_t b0, uint32_t b1) {
    asm volatile(
        "mma.sync.aligned.m16n8k8.row.col.f32.tf32.tf32.f32 "
        "{%0,%1,%2,%3}, {%4,%5,%6,%7}, {%8,%9}, {%0,%1,%2,%3};"
        : "+f"(c[0]), "+f"(c[1]), "+f"(c[2]), "+f"(c[3])
        : "r"(a0), "r"(a1), "r"(a2), "r"(a3), "r"(b0), "r"(b1));
}

// ---------------------------------------------------------------------------
// C = A @ B^T via tf32 tensor cores. A [M,K] rm, B [N,K] rm.
// 128x128 block, BK=16, 8 warps of 64x32, m16n8k8 fragments.
// MODE 0: A = x, scatter to g_q/g_k/g_v.  MODE 1: A = g_att, write C.
// ---------------------------------------------------------------------------
#define GP 20   // smem pitch (floats); 20 mod 32 => conflict-free frag loads

template<int MODE>
__global__ __launch_bounds__(256) void tgemm(const float* __restrict__ A,
                                             const float* __restrict__ B,
                                             float* __restrict__ C,
                                             int M, int N, int K) {
    __shared__ float As[128*GP];
    __shared__ float Bs[128*GP];

    const int t = threadIdx.x;
    const int w = t >> 5, l = t & 31, g = l >> 2, q = l & 3;
    const int wm = (w >> 2) * 64;   // 0 or 64
    const int wn = (w & 3) * 32;    // 0,32,64,96
    const int m0 = blockIdx.y * 128, n0 = blockIdx.x * 128;

    const float* Ap = (MODE == 1) ? g_att : A;

    float acc[4][4][4];
#pragma unroll
    for (int mi = 0; mi < 4; mi++)
#pragma unroll
        for (int ni = 0; ni < 4; ni++)
#pragma unroll
            for (int c = 0; c < 4; c++) acc[mi][ni][c] = 0.f;

    for (int kt = 0; kt < K; kt += 16) {
        __syncthreads();
        // 512 float4 per matrix per tile; 2 per thread
        for (int i = t; i < 512; i += 256) {
            int r = i >> 2, c4 = (i & 3) << 2;
            float4 av = *(const float4*)(Ap + (size_t)(m0 + r) * K + kt + c4);
            As[r*GP + c4 + 0] = f2tf(av.x); As[r*GP + c4 + 1] = f2tf(av.y);
            As[r*GP + c4 + 2] = f2tf(av.z); As[r*GP + c4 + 3] = f2tf(av.w);
            float4 bv = *(const float4*)(B + (size_t)(n0 + r) * K + kt + c4);
            Bs[r*GP + c4 + 0] = f2tf(bv.x); Bs[r*GP + c4 + 1] = f2tf(bv.y);
            Bs[r*GP + c4 + 2] = f2tf(bv.z); Bs[r*GP + c4 + 3] = f2tf(bv.w);
        }
        __syncthreads();

#pragma unroll
        for (int ks = 0; ks < 16; ks += 8) {
            uint32_t af[4][4], bf[4][2];
#pragma unroll
            for (int mi = 0; mi < 4; mi++) {
                int r0 = wm + mi*16 + g;
                af[mi][0] = __float_as_uint(As[r0*GP + ks + q]);
                af[mi][1] = __float_as_uint(As[(r0+8)*GP + ks + q]);
                af[mi][2] = __float_as_uint(As[r0*GP + ks + q + 4]);
                af[mi][3] = __float_as_uint(As[(r0+8)*GP + ks + q + 4]);
            }
#pragma unroll
            for (int ni = 0; ni < 4; ni++) {
                int r0 = wn + ni*8 + g;
                bf[ni][0] = __float_as_uint(Bs[r0*GP + ks + q]);
                bf[ni][1] = __float_as_uint(Bs[r0*GP + ks + q + 4]);
            }
#pragma unroll
            for (int mi = 0; mi < 4; mi++)
#pragma unroll
                for (int ni = 0; ni < 4; ni++)
                    mma8(acc[mi][ni], af[mi][0], af[mi][1], af[mi][2], af[mi][3],
                         bf[ni][0], bf[ni][1]);
        }
    }

#pragma unroll
    for (int mi = 0; mi < 4; mi++) {
        int gr0 = m0 + wm + mi*16 + g;      // rows for c0/c1
        int gr1 = gr0 + 8;                  // rows for c2/c3
#pragma unroll
        for (int ni = 0; ni < 4; ni++) {
            int col = n0 + wn + ni*8;       // 8-wide tile, never straddles head
            if (MODE == 0) {
                int which = col / EMBED;
                int rem   = col - which * EMBED;
                int h     = rem / HDIM;
                int d0    = rem - h * HDIM + 2*q;
                float* dst = (which == 0) ? g_q : (which == 1) ? g_k : g_v;
                int b0i = gr0 >> 12, n0i = gr0 & 4095;
                int b1i = gr1 >> 12, n1i = gr1 & 4095;
                size_t i0 = (((size_t)(b0i*NHEAD + h))*SEQ + n0i)*HDIM + d0;
                size_t i1 = (((size_t)(b1i*NHEAD + h))*SEQ + n1i)*HDIM + d0;
                *(float2*)(dst + i0) = make_float2(acc[mi][ni][0], acc[mi][ni][1]);
                *(float2*)(dst + i1) = make_float2(acc[mi][ni][2], acc[mi][ni][3]);
            } else {
                size_t i0 = (size_t)gr0 * N + col + 2*q;
                size_t i1 = (size_t)gr1 * N + col + 2*q;
                *(float2*)(C + i0) = make_float2(acc[mi][ni][0], acc[mi][ni][1]);
                *(float2*)(C + i1) = make_float2(acc[mi][ni][2], acc[mi][ni][3]);
            }
        }
    }
}

// ---------------------------------------------------------------------------
// Flash attention, tf32 MMA + fp32 softmax. Grid (SEQ/64, B*H), 256 threads.
// BM=BN=64, D=96. Warp grid 4(m)x2(n). Pitches: Q/K 100, V 104, S 68 —
// all fragment LDS patterns bank-conflict-free.
// ---------------------------------------------------------------------------
#define PQ 100
#define PV 104
#define PS 68

__global__ __launch_bounds__(256) void flash_tf32() {
    extern __shared__ float sm[];
    float* Qs   = sm;                  // 64*PQ
    float* Ks   = Qs + 64*PQ;          // 64*PQ
    float* Vs   = Ks + 64*PQ;          // 64*PV
    float* Ss   = Vs + 64*PV;          // 64*PS
    float* mrow = Ss + 64*PS;
    float* lrow = mrow + 64;
    float* srow = lrow + 64;

    const int t = threadIdx.x;
    const int w = t >> 5, l = t & 31, g = l >> 2, q = l & 3;
    const int wm = (w >> 1) * 16;      // 0,16,32,48
    const int wn = w & 1;              // 0,1
    const int bh = blockIdx.y;
    const int q0 = blockIdx.x * 64;

    const float* Qg = g_q + (size_t)bh * SEQ * HDIM;
    const float* Kg = g_k + (size_t)bh * SEQ * HDIM;
    const float* Vg = g_v + (size_t)bh * SEQ * HDIM;

    // Q tile: 64 x 96 = 384 float4
    for (int i = t; i < 64*24; i += 256) {
        int r = i / 24, c = (i % 24) * 4;
        float4 v = *(const float4*)(Qg + (size_t)(q0 + r) * HDIM + c);
        float* p = &Qs[r*PQ + c];
        p[0] = f2tf(v.x); p[1] = f2tf(v.y); p[2] = f2tf(v.z); p[3] = f2tf(v.w);
    }
    if (t < 64) { mrow[t] = -INFINITY; lrow[t] = 0.f; }

    float oacc[6][4];
#pragma unroll
    for (int ni = 0; ni < 6; ni++)
#pragma unroll
        for (int c = 0; c < 4; c++) oacc[ni][c] = 0.f;

    for (int kt = 0; kt < SEQ; kt += 64) {
        __syncthreads();
        for (int i = t; i < 64*24; i += 256) {
            int r = i / 24, c = (i % 24) * 4;
            float4 kv = *(const float4*)(Kg + (size_t)(kt + r) * HDIM + c);
            float* pk = &Ks[r*PQ + c];
            pk[0] = f2tf(kv.x); pk[1] = f2tf(kv.y); pk[2] = f2tf(kv.z); pk[3] = f2tf(kv.w);
            float4 vv = *(const float4*)(Vg + (size_t)(kt + r) * HDIM + c);
            float* pv = &Vs[r*PV + c];
            pv[0] = f2tf(vv.x); pv[1] = f2tf(vv.y); pv[2] = f2tf(vv.z); pv[3] = f2tf(vv.w);
        }
        __syncthreads();

        // ---- S = Q K^T (warp tile 16 x 32) ----
        float sacc[4][4];
#pragma unroll
        for (int ni = 0; ni < 4; ni++)
#pragma unroll
            for (int c = 0; c < 4; c++) sacc[ni][c] = 0.f;

#pragma unroll
        for (int d0 = 0; d0 < HDIM; d0 += 8) {
            uint32_t a0 = __float_as_uint(Qs[(wm+g)*PQ + d0 + q]);
            uint32_t a1 = __float_as_uint(Qs[(wm+8+g)*PQ + d0 + q]);
            uint32_t a2 = __float_as_uint(Qs[(wm+g)*PQ + d0 + q + 4]);
            uint32_t a3 = __float_as_uint(Qs[(wm+8+g)*PQ + d0 + q + 4]);
#pragma unroll
            for (int ni = 0; ni < 4; ni++) {
                int r0 = wn*32 + ni*8 + g;
                uint32_t b0 = __float_as_uint(Ks[r0*PQ + d0 + q]);
                uint32_t b1 = __float_as_uint(Ks[r0*PQ + d0 + q + 4]);
                mma8(sacc[ni], a0, a1, a2, a3, b0, b1);
            }
        }
#pragma unroll
        for (int ni = 0; ni < 4; ni++) {
            int col = wn*32 + ni*8 + 2*q;
            *(float2*)&Ss[(wm+g)*PS + col] =
                make_float2(sacc[ni][0]*SCALE_F, sacc[ni][1]*SCALE_F);
            *(float2*)&Ss[(wm+8+g)*PS + col] =
                make_float2(sacc[ni][2]*SCALE_F, sacc[ni][3]*SCALE_F);
        }
        __syncthreads();

        // ---- online softmax: 4 threads per row + butterfly reduce ----
        {
            int row = t >> 2, sg = t & 3;
            float* rp = &Ss[row*PS + sg*16];
            float mold = mrow[row];
            float tm = -INFINITY;
#pragma unroll
            for (int k2 = 0; k2 < 16; k2++) tm = fmaxf(tm, rp[k2]);
            tm = fmaxf(tm, __shfl_xor_sync(0xffffffffu, tm, 1));
            tm = fmaxf(tm, __shfl_xor_sync(0xffffffffu, tm, 2));
            float mn = fmaxf(mold, tm);
            float ts = 0.f;
#pragma unroll
            for (int k2 = 0; k2 < 16; k2++) {
                float p = __expf(rp[k2] - mn);
                rp[k2] = f2tf(p);
                ts += p;
            }
            ts += __shfl_xor_sync(0xffffffffu, ts, 1);
            ts += __shfl_xor_sync(0xffffffffu, ts, 2);
            if (sg == 0) {
                float sc = __expf(mold - mn);
                srow[row] = sc;
                lrow[row] = lrow[row] * sc + ts;
                mrow[row] = mn;
            }
        }
        __syncthreads();

        // ---- O = O*sc + P @ V (warp tile 16 x 48) ----
        {
            float s0 = srow[wm+g], s1 = srow[wm+8+g];
#pragma unroll
            for (int ni = 0; ni < 6; ni++) {
                oacc[ni][0] *= s0; oacc[ni][1] *= s0;
                oacc[ni][2] *= s1; oacc[ni][3] *= s1;
            }
        }
#pragma unroll
        for (int k0 = 0; k0 < 64; k0 += 8) {
            uint32_t a0 = __float_as_uint(Ss[(wm+g)*PS + k0 + q]);
            uint32_t a1 = __float_as_uint(Ss[(wm+8+g)*PS + k0 + q]);
            uint32_t a2 = __float_as_uint(Ss[(wm+g)*PS + k0 + q + 4]);
            uint32_t a3 = __float_as_uint(Ss[(wm+8+g)*PS + k0 + q + 4]);
#pragma unroll
            for (int ni = 0; ni < 6; ni++) {
                int cn = wn*48 + ni*8 + g;
                uint32_t b0 = __float_as_uint(Vs[(k0+q)*PV + cn]);
                uint32_t b1 = __float_as_uint(Vs[(k0+4+q)*PV + cn]);
                mma8(oacc[ni], a0, a1, a2, a3, b0, b1);
            }
        }
    }

    // epilogue: normalize + write [B, N, H*D]
    const int b = bh >> 3, h = bh & 7;
    float inv0 = 1.f / lrow[wm+g];
    float inv1 = 1.f / lrow[wm+8+g];
#pragma unroll
    for (int ni = 0; ni < 6; ni++) {
        int d = wn*48 + ni*8 + 2*q;
        size_t r0 = ((size_t)(b*SEQ + q0 + wm + g))*EMBED + h*HDIM + d;
        size_t r1 = ((size_t)(b*SEQ + q0 + wm + 8 + g))*EMBED + h*HDIM + d;
        *(float2*)(g_att + r0) = make_float2(oacc[ni][0]*inv0, oacc[ni][1]*inv0);
        *(float2*)(g_att + r1) = make_float2(oacc[ni][2]*inv1, oacc[ni][3]*inv1);
    }
}

static const int FLASH_SMEM = (2*64*PQ + 64*PV + 64*PS + 3*64) * (int)sizeof(float); // 96000

extern "C" void kernel_launch(void* const* d_in, const int* in_sizes, int n_in,
                              void* d_out, int out_size) {
    const float* x      = (const float*)d_in[0];   // [2,4096,768]
    const float* w_qkv  = (const float*)d_in[1];   // [2304,768]
    const float* w_proj = (const float*)d_in[2];   // [768,768]
    float* out = (float*)d_out;                    // [2,4096,768]

    static bool attr_set = false;
    if (!attr_set) {
        cudaFuncSetAttribute(flash_tf32, cudaFuncAttributeMaxDynamicSharedMemorySize,
                             FLASH_SMEM);
        attr_set = true;
    }

    tgemm<0><<<dim3(QKV_N/128, MTOT/128), 256>>>(x, w_qkv, nullptr,
                                                 MTOT, QKV_N, EMBED);
    flash_tf32<<<dim3(SEQ/64, BATCH*NHEAD), 256, FLASH_SMEM>>>();
    tgemm<1><<<dim3(EMBED/128, MTOT/128), 256>>>(nullptr, w_proj, out,
                                                 MTOT, EMBED, EMBED);
}

// round 6
// speedup vs baseline: 3.6287x; 1.5873x over previous
#include <cuda_runtime.h>
#include <math.h>
#include <stdint.h>

#define BATCH 2
#define SEQ   4096
#define EMBED 768
#define NHEAD 8
#define HDIM  96
#define MTOT  (BATCH*SEQ)          // 8192
#define QKV_N (3*EMBED)            // 2304
#define SCALE_F 0.10206207261596575f  // 96^-0.5

// Scratch (device globals; allocation is forbidden)
__device__ float g_q[(size_t)BATCH*NHEAD*SEQ*HDIM];   // [B,H,N,D] (tf32-rounded)
__device__ float g_k[(size_t)BATCH*NHEAD*SEQ*HDIM];
__device__ float g_v[(size_t)BATCH*NHEAD*SEQ*HDIM];
__device__ float g_att[(size_t)MTOT*EMBED];           // [B*N, C]

__device__ __forceinline__ float f2tf(float x) {
    uint32_t u;
    asm("cvt.rna.tf32.f32 %0, %1;" : "=r"(u) : "f"(x));
    return __uint_as_float(u);
}

// D = A(16x8,row) * B(8x8,col) + D, tf32 inputs, f32 accum.
__device__ __forceinline__ void mma8(float* c, uint32_t a0, uint32_t a1,
                                     uint32_t a2, uint32_t a3,
                                     uint32_t b0, uint32_t b1) {
    asm volatile(
        "mma.sync.aligned.m16n8k8.row.col.f32.tf32.tf32.f32 "
        "{%0,%1,%2,%3}, {%4,%5,%6,%7}, {%8,%9}, {%0,%1,%2,%3};"
        : "+f"(c[0]), "+f"(c[1]), "+f"(c[2]), "+f"(c[3])
        : "r"(a0), "r"(a1), "r"(a2), "r"(a3), "r"(b0), "r"(b1));
}

__device__ __forceinline__ void cpasync16(uint32_t dst, const void* src) {
    asm volatile("cp.async.cg.shared.global [%0], [%1], 16;\n"
                 :: "r"(dst), "l"(src));
}

// ---------------------------------------------------------------------------
// C = A @ B^T via tf32 MMA. 128x128 block, BK=16, 8 warps of 64x32.
// Register double-buffered global loads. MODE 0 scatters + tf32-rounds q/k/v.
// ---------------------------------------------------------------------------
#define GP 20

template<int MODE>
__global__ __launch_bounds__(256) void tgemm(const float* __restrict__ A,
                                             const float* __restrict__ B,
                                             float* __restrict__ C,
                                             int M, int N, int K) {
    __shared__ float As[128*GP];
    __shared__ float Bs[128*GP];

    const int t = threadIdx.x;
    const int w = t >> 5, l = t & 31, g = l >> 2, q = l & 3;
    const int wm = (w >> 2) * 64;
    const int wn = (w & 3) * 32;
    const int m0 = blockIdx.y * 128, n0 = blockIdx.x * 128;

    const float* Ap = (MODE == 1) ? g_att : A;

    float acc[4][4][4];
#pragma unroll
    for (int mi = 0; mi < 4; mi++)
#pragma unroll
        for (int ni = 0; ni < 4; ni++)
#pragma unroll
            for (int c = 0; c < 4; c++) acc[mi][ni][c] = 0.f;

    const int rs = t >> 2, cs = (t & 3) << 2;
    const float* aP0 = Ap + (size_t)(m0 + rs) * K + cs;
    const float* aP1 = Ap + (size_t)(m0 + rs + 64) * K + cs;
    const float* bP0 = B  + (size_t)(n0 + rs) * K + cs;
    const float* bP1 = B  + (size_t)(n0 + rs + 64) * K + cs;

    float4 sa0 = *(const float4*)(aP0);
    float4 sa1 = *(const float4*)(aP1);
    float4 sb0 = *(const float4*)(bP0);
    float4 sb1 = *(const float4*)(bP1);

    for (int kt = 0; kt < K; kt += 16) {
        __syncthreads();
        As[rs*GP+cs+0] = f2tf(sa0.x); As[rs*GP+cs+1] = f2tf(sa0.y);
        As[rs*GP+cs+2] = f2tf(sa0.z); As[rs*GP+cs+3] = f2tf(sa0.w);
        As[(rs+64)*GP+cs+0] = f2tf(sa1.x); As[(rs+64)*GP+cs+1] = f2tf(sa1.y);
        As[(rs+64)*GP+cs+2] = f2tf(sa1.z); As[(rs+64)*GP+cs+3] = f2tf(sa1.w);
        Bs[rs*GP+cs+0] = f2tf(sb0.x); Bs[rs*GP+cs+1] = f2tf(sb0.y);
        Bs[rs*GP+cs+2] = f2tf(sb0.z); Bs[rs*GP+cs+3] = f2tf(sb0.w);
        Bs[(rs+64)*GP+cs+0] = f2tf(sb1.x); Bs[(rs+64)*GP+cs+1] = f2tf(sb1.y);
        Bs[(rs+64)*GP+cs+2] = f2tf(sb1.z); Bs[(rs+64)*GP+cs+3] = f2tf(sb1.w);
        __syncthreads();

        if (kt + 16 < K) {
            sa0 = *(const float4*)(aP0 + kt + 16);
            sa1 = *(const float4*)(aP1 + kt + 16);
            sb0 = *(const float4*)(bP0 + kt + 16);
            sb1 = *(const float4*)(bP1 + kt + 16);
        }

#pragma unroll
        for (int ks = 0; ks < 16; ks += 8) {
            uint32_t af[4][4], bf[4][2];
#pragma unroll
            for (int mi = 0; mi < 4; mi++) {
                int r0 = wm + mi*16 + g;
                af[mi][0] = __float_as_uint(As[r0*GP + ks + q]);
                af[mi][1] = __float_as_uint(As[(r0+8)*GP + ks + q]);
                af[mi][2] = __float_as_uint(As[r0*GP + ks + q + 4]);
                af[mi][3] = __float_as_uint(As[(r0+8)*GP + ks + q + 4]);
            }
#pragma unroll
            for (int ni = 0; ni < 4; ni++) {
                int r0 = wn + ni*8 + g;
                bf[ni][0] = __float_as_uint(Bs[r0*GP + ks + q]);
                bf[ni][1] = __float_as_uint(Bs[r0*GP + ks + q + 4]);
            }
#pragma unroll
            for (int mi = 0; mi < 4; mi++)
#pragma unroll
                for (int ni = 0; ni < 4; ni++)
                    mma8(acc[mi][ni], af[mi][0], af[mi][1], af[mi][2], af[mi][3],
                         bf[ni][0], bf[ni][1]);
        }
    }

#pragma unroll
    for (int mi = 0; mi < 4; mi++) {
        int gr0 = m0 + wm + mi*16 + g;
        int gr1 = gr0 + 8;
#pragma unroll
        for (int ni = 0; ni < 4; ni++) {
            int col = n0 + wn + ni*8;
            if (MODE == 0) {
                int which = col / EMBED;
                int rem   = col - which * EMBED;
                int h     = rem / HDIM;
                int d0    = rem - h * HDIM + 2*q;
                float* dst = (which == 0) ? g_q : (which == 1) ? g_k : g_v;
                int b0i = gr0 >> 12, n0i = gr0 & 4095;
                int b1i = gr1 >> 12, n1i = gr1 & 4095;
                size_t i0 = (((size_t)(b0i*NHEAD + h))*SEQ + n0i)*HDIM + d0;
                size_t i1 = (((size_t)(b1i*NHEAD + h))*SEQ + n1i)*HDIM + d0;
                // tf32-round here so flash can cp.async raw tiles
                *(float2*)(dst + i0) = make_float2(f2tf(acc[mi][ni][0]), f2tf(acc[mi][ni][1]));
                *(float2*)(dst + i1) = make_float2(f2tf(acc[mi][ni][2]), f2tf(acc[mi][ni][3]));
            } else {
                size_t i0 = (size_t)gr0 * N + col + 2*q;
                size_t i1 = (size_t)gr1 * N + col + 2*q;
                *(float2*)(C + i0) = make_float2(acc[mi][ni][0], acc[mi][ni][1]);
                *(float2*)(C + i1) = make_float2(acc[mi][ni][2], acc[mi][ni][3]);
            }
        }
    }
}

// ---------------------------------------------------------------------------
// Flash attention v2. Grid (SEQ/128, B*H), 256 threads, 1 CTA/SM.
// BM=128, BN=64. Warp = 16 rows x full width. Q + softmax state in registers.
// cp.async double-buffered K/V. P via smem for the PV A-fragments.
// ---------------------------------------------------------------------------
#define FPK 100   // K pitch: S B-frag banks (4g+q) bijective
#define FPV 104   // V pitch: PV B-frag banks (8q+g) bijective
#define FPS 68    // P pitch: PV A-frag banks (4g+q) bijective

__global__ __launch_bounds__(256, 1) void flash2() {
    extern __shared__ float sm[];
    float* Kb = sm;                      // 2 * 64*FPK
    float* Vb = Kb + 2*64*FPK;           // 2 * 64*FPV
    float* Ps = Vb + 2*64*FPV;           // 128*FPS

    const int t = threadIdx.x;
    const int w = t >> 5, l = t & 31, g = l >> 2, q = l & 3;
    const int wm = w * 16;
    const int bh = blockIdx.y;
    const int q0 = blockIdx.x * 128;

    const float* Qg = g_q + (size_t)bh * SEQ * HDIM;
    const float* Kg = g_k + (size_t)bh * SEQ * HDIM;
    const float* Vg = g_v + (size_t)bh * SEQ * HDIM;

    const uint32_t kb_s = (uint32_t)__cvta_generic_to_shared(Kb);
    const uint32_t vb_s = (uint32_t)__cvta_generic_to_shared(Vb);

    // issue cp.async for one K/V tile (64 rows x 96 floats each) into stage s
    auto load_tile = [&](int s, int kt) {
#pragma unroll
        for (int j = 0; j < 6; j++) {
            int i = t + j*256;                  // 0..1535
            int r = i / 24, c = (i - r*24) * 4;
            cpasync16(kb_s + (uint32_t)((s*64*FPK + r*FPK + c) * 4),
                      Kg + (size_t)(kt + r) * HDIM + c);
            cpasync16(vb_s + (uint32_t)((s*64*FPV + r*FPV + c) * 4),
                      Vg + (size_t)(kt + r) * HDIM + c);
        }
        asm volatile("cp.async.commit_group;\n" ::);
    };

    load_tile(0, 0);

    // Q fragments in registers (pre-rounded tf32 in gmem)
    uint32_t qf[12][4];
    {
        const float* Qr0 = Qg + (size_t)(q0 + wm + g) * HDIM;
        const float* Qr1 = Qr0 + 8 * HDIM;
#pragma unroll
        for (int kk = 0; kk < 12; kk++) {
            qf[kk][0] = __float_as_uint(Qr0[8*kk + q]);
            qf[kk][1] = __float_as_uint(Qr1[8*kk + q]);
            qf[kk][2] = __float_as_uint(Qr0[8*kk + q + 4]);
            qf[kk][3] = __float_as_uint(Qr1[8*kk + q + 4]);
        }
    }

    float of[12][4];
#pragma unroll
    for (int ni = 0; ni < 12; ni++)
#pragma unroll
        for (int c = 0; c < 4; c++) of[ni][c] = 0.f;
    float m0 = -INFINITY, m1 = -INFINITY, l0 = 0.f, l1 = 0.f;

    asm volatile("cp.async.wait_group 0;\n" ::);
    __syncthreads();

    for (int it = 0; it < SEQ/64; it++) {
        const float* Kc = Kb + (it & 1) * 64*FPK;
        const float* Vc = Vb + (it & 1) * 64*FPV;

        // ---- S = Q K^T : warp tile 16 x 64 ----
        float sacc[8][4];
#pragma unroll
        for (int ni = 0; ni < 8; ni++)
#pragma unroll
            for (int c = 0; c < 4; c++) sacc[ni][c] = 0.f;
#pragma unroll
        for (int kk = 0; kk < 12; kk++) {
#pragma unroll
            for (int ni = 0; ni < 8; ni++) {
                uint32_t b0 = __float_as_uint(Kc[(8*ni + g)*FPK + 8*kk + q]);
                uint32_t b1 = __float_as_uint(Kc[(8*ni + g)*FPK + 8*kk + q + 4]);
                mma8(sacc[ni], qf[kk][0], qf[kk][1], qf[kk][2], qf[kk][3], b0, b1);
            }
        }

        // ---- register online softmax (rows wm+g and wm+8+g) ----
        float tm0 = -INFINITY, tm1 = -INFINITY;
#pragma unroll
        for (int ni = 0; ni < 8; ni++) {
            tm0 = fmaxf(tm0, fmaxf(sacc[ni][0], sacc[ni][1]));
            tm1 = fmaxf(tm1, fmaxf(sacc[ni][2], sacc[ni][3]));
        }
        tm0 = fmaxf(tm0, __shfl_xor_sync(0xffffffffu, tm0, 1));
        tm0 = fmaxf(tm0, __shfl_xor_sync(0xffffffffu, tm0, 2));
        tm1 = fmaxf(tm1, __shfl_xor_sync(0xffffffffu, tm1, 1));
        tm1 = fmaxf(tm1, __shfl_xor_sync(0xffffffffu, tm1, 2));
        float mn0 = fmaxf(m0, tm0), mn1 = fmaxf(m1, tm1);
        float sc0 = __expf((m0 - mn0) * SCALE_F);
        float sc1 = __expf((m1 - mn1) * SCALE_F);
        float s0 = 0.f, s1 = 0.f;
#pragma unroll
        for (int ni = 0; ni < 8; ni++) {
            float p00 = __expf((sacc[ni][0] - mn0) * SCALE_F);
            float p01 = __expf((sacc[ni][1] - mn0) * SCALE_F);
            float p10 = __expf((sacc[ni][2] - mn1) * SCALE_F);
            float p11 = __expf((sacc[ni][3] - mn1) * SCALE_F);
            s0 += p00 + p01; s1 += p10 + p11;
            *(float2*)&Ps[(wm+g)*FPS + 8*ni + 2*q]   = make_float2(f2tf(p00), f2tf(p01));
            *(float2*)&Ps[(wm+8+g)*FPS + 8*ni + 2*q] = make_float2(f2tf(p10), f2tf(p11));
        }
        s0 += __shfl_xor_sync(0xffffffffu, s0, 1);
        s0 += __shfl_xor_sync(0xffffffffu, s0, 2);
        s1 += __shfl_xor_sync(0xffffffffu, s1, 1);
        s1 += __shfl_xor_sync(0xffffffffu, s1, 2);
        l0 = l0 * sc0 + s0; m0 = mn0;
        l1 = l1 * sc1 + s1; m1 = mn1;
#pragma unroll
        for (int ni = 0; ni < 12; ni++) {
            of[ni][0] *= sc0; of[ni][1] *= sc0;
            of[ni][2] *= sc1; of[ni][3] *= sc1;
        }
        __syncthreads();   // P visible; all K-reads of this stage done

        if (it < SEQ/64 - 1) load_tile((it + 1) & 1, (it + 1) * 64);

        // ---- O += P @ V : warp tile 16 x 96 ----
#pragma unroll
        for (int kk2 = 0; kk2 < 8; kk2++) {
            uint32_t a0 = __float_as_uint(Ps[(wm+g)*FPS + 8*kk2 + q]);
            uint32_t a1 = __float_as_uint(Ps[(wm+8+g)*FPS + 8*kk2 + q]);
            uint32_t a2 = __float_as_uint(Ps[(wm+g)*FPS + 8*kk2 + q + 4]);
            uint32_t a3 = __float_as_uint(Ps[(wm+8+g)*FPS + 8*kk2 + q + 4]);
#pragma unroll
            for (int ni = 0; ni < 12; ni++) {
                uint32_t b0 = __float_as_uint(Vc[(8*kk2 + q)*FPV + 8*ni + g]);
                uint32_t b1 = __float_as_uint(Vc[(8*kk2 + 4 + q)*FPV + 8*ni + g]);
                mma8(of[ni], a0, a1, a2, a3, b0, b1);
            }
        }

        if (it < SEQ/64 - 1) asm volatile("cp.async.wait_group 0;\n" ::);
        __syncthreads();   // all V/P reads done before next P store / buffer reuse
    }

    // epilogue: normalize + write [B, N, H*D]
    const int b = bh >> 3, h = bh & 7;
    float inv0 = 1.f / l0, inv1 = 1.f / l1;
    size_t r0 = ((size_t)(b*SEQ + q0 + wm + g)) * EMBED + h*HDIM;
    size_t r1 = r0 + (size_t)8 * EMBED;
#pragma unroll
    for (int ni = 0; ni < 12; ni++) {
        *(float2*)(g_att + r0 + 8*ni + 2*q) =
            make_float2(of[ni][0]*inv0, of[ni][1]*inv0);
        *(float2*)(g_att + r1 + 8*ni + 2*q) =
            make_float2(of[ni][2]*inv1, of[ni][3]*inv1);
    }
}

static const int FLASH_SMEM = (2*64*FPK + 2*64*FPV + 128*FPS) * (int)sizeof(float); // 139264

extern "C" void kernel_launch(void* const* d_in, const int* in_sizes, int n_in,
                              void* d_out, int out_size) {
    const float* x      = (const float*)d_in[0];   // [2,4096,768]
    const float* w_qkv  = (const float*)d_in[1];   // [2304,768]
    const float* w_proj = (const float*)d_in[2];   // [768,768]
    float* out = (float*)d_out;                    // [2,4096,768]

    static bool attr_set = false;
    if (!attr_set) {
        cudaFuncSetAttribute(flash2, cudaFuncAttributeMaxDynamicSharedMemorySize,
                             FLASH_SMEM);
        attr_set = true;
    }

    tgemm<0><<<dim3(QKV_N/128, MTOT/128), 256>>>(x, w_qkv, nullptr,
                                                 MTOT, QKV_N, EMBED);
    flash2<<<dim3(SEQ/128, BATCH*NHEAD), 256, FLASH_SMEM>>>();
    tgemm<1><<<dim3(EMBED/128, MTOT/128), 256>>>(nullptr, w_proj, out,
                                                 MTOT, EMBED, EMBED);
}

// round 7
// speedup vs baseline: 4.4025x; 1.2133x over previous
#include <cuda_runtime.h>
#include <math.h>
#include <stdint.h>

#define BATCH 2
#define SEQ   4096
#define EMBED 768
#define NHEAD 8
#define HDIM  96
#define MTOT  (BATCH*SEQ)          // 8192
#define QKV_N (3*EMBED)            // 2304
#define SCALE_F 0.10206207261596575f  // 96^-0.5
#define C2EXP  0.14724446f            // SCALE_F * log2(e)

// Scratch (device globals; allocation is forbidden)
__device__ float g_q[(size_t)BATCH*NHEAD*SEQ*HDIM];   // [B,H,N,D] (tf32-rounded)
__device__ float g_k[(size_t)BATCH*NHEAD*SEQ*HDIM];
__device__ float g_v[(size_t)BATCH*NHEAD*SEQ*HDIM];
__device__ float g_att[(size_t)MTOT*EMBED];           // [B*N, C]

__device__ __forceinline__ float f2tf(float x) {
    uint32_t u;
    asm("cvt.rna.tf32.f32 %0, %1;" : "=r"(u) : "f"(x));
    return __uint_as_float(u);
}

// D = A(16x8,row) * B(8x8,col) + D, tf32 inputs, f32 accum.
__device__ __forceinline__ void mma8(float* c, uint32_t a0, uint32_t a1,
                                     uint32_t a2, uint32_t a3,
                                     uint32_t b0, uint32_t b1) {
    asm volatile(
        "mma.sync.aligned.m16n8k8.row.col.f32.tf32.tf32.f32 "
        "{%0,%1,%2,%3}, {%4,%5,%6,%7}, {%8,%9}, {%0,%1,%2,%3};"
        : "+f"(c[0]), "+f"(c[1]), "+f"(c[2]), "+f"(c[3])
        : "r"(a0), "r"(a1), "r"(a2), "r"(a3), "r"(b0), "r"(b1));
}

__device__ __forceinline__ void cpasync16(uint32_t dst, const void* src) {
    asm volatile("cp.async.cg.shared.global [%0], [%1], 16;\n"
                 :: "r"(dst), "l"(src));
}

// ---------------------------------------------------------------------------
// C = A @ B^T via tf32 MMA. 128x128 block, BK=16, 8 warps of 64x32.
// Register double-buffered global loads. MODE 0 scatters + tf32-rounds q/k/v.
// ---------------------------------------------------------------------------
#define GP 20

template<int MODE>
__global__ __launch_bounds__(256) void tgemm(const float* __restrict__ A,
                                             const float* __restrict__ B,
                                             float* __restrict__ C,
                                             int M, int N, int K) {
    __shared__ float As[128*GP];
    __shared__ float Bs[128*GP];

    const int t = threadIdx.x;
    const int w = t >> 5, l = t & 31, g = l >> 2, q = l & 3;
    const int wm = (w >> 2) * 64;
    const int wn = (w & 3) * 32;
    const int m0 = blockIdx.y * 128, n0 = blockIdx.x * 128;

    const float* Ap = (MODE == 1) ? g_att : A;

    float acc[4][4][4];
#pragma unroll
    for (int mi = 0; mi < 4; mi++)
#pragma unroll
        for (int ni = 0; ni < 4; ni++)
#pragma unroll
            for (int c = 0; c < 4; c++) acc[mi][ni][c] = 0.f;

    const int rs = t >> 2, cs = (t & 3) << 2;
    const float* aP0 = Ap + (size_t)(m0 + rs) * K + cs;
    const float* aP1 = Ap + (size_t)(m0 + rs + 64) * K + cs;
    const float* bP0 = B  + (size_t)(n0 + rs) * K + cs;
    const float* bP1 = B  + (size_t)(n0 + rs + 64) * K + cs;

    float4 sa0 = *(const float4*)(aP0);
    float4 sa1 = *(const float4*)(aP1);
    float4 sb0 = *(const float4*)(bP0);
    float4 sb1 = *(const float4*)(bP1);

    for (int kt = 0; kt < K; kt += 16) {
        __syncthreads();
        As[rs*GP+cs+0] = f2tf(sa0.x); As[rs*GP+cs+1] = f2tf(sa0.y);
        As[rs*GP+cs+2] = f2tf(sa0.z); As[rs*GP+cs+3] = f2tf(sa0.w);
        As[(rs+64)*GP+cs+0] = f2tf(sa1.x); As[(rs+64)*GP+cs+1] = f2tf(sa1.y);
        As[(rs+64)*GP+cs+2] = f2tf(sa1.z); As[(rs+64)*GP+cs+3] = f2tf(sa1.w);
        Bs[rs*GP+cs+0] = f2tf(sb0.x); Bs[rs*GP+cs+1] = f2tf(sb0.y);
        Bs[rs*GP+cs+2] = f2tf(sb0.z); Bs[rs*GP+cs+3] = f2tf(sb0.w);
        Bs[(rs+64)*GP+cs+0] = f2tf(sb1.x); Bs[(rs+64)*GP+cs+1] = f2tf(sb1.y);
        Bs[(rs+64)*GP+cs+2] = f2tf(sb1.z); Bs[(rs+64)*GP+cs+3] = f2tf(sb1.w);
        __syncthreads();

        if (kt + 16 < K) {
            sa0 = *(const float4*)(aP0 + kt + 16);
            sa1 = *(const float4*)(aP1 + kt + 16);
            sb0 = *(const float4*)(bP0 + kt + 16);
            sb1 = *(const float4*)(bP1 + kt + 16);
        }

#pragma unroll
        for (int ks = 0; ks < 16; ks += 8) {
            uint32_t af[4][4], bf[4][2];
#pragma unroll
            for (int mi = 0; mi < 4; mi++) {
                int r0 = wm + mi*16 + g;
                af[mi][0] = __float_as_uint(As[r0*GP + ks + q]);
                af[mi][1] = __float_as_uint(As[(r0+8)*GP + ks + q]);
                af[mi][2] = __float_as_uint(As[r0*GP + ks + q + 4]);
                af[mi][3] = __float_as_uint(As[(r0+8)*GP + ks + q + 4]);
            }
#pragma unroll
            for (int ni = 0; ni < 4; ni++) {
                int r0 = wn + ni*8 + g;
                bf[ni][0] = __float_as_uint(Bs[r0*GP + ks + q]);
                bf[ni][1] = __float_as_uint(Bs[r0*GP + ks + q + 4]);
            }
#pragma unroll
            for (int mi = 0; mi < 4; mi++)
#pragma unroll
                for (int ni = 0; ni < 4; ni++)
                    mma8(acc[mi][ni], af[mi][0], af[mi][1], af[mi][2], af[mi][3],
                         bf[ni][0], bf[ni][1]);
        }
    }

#pragma unroll
    for (int mi = 0; mi < 4; mi++) {
        int gr0 = m0 + wm + mi*16 + g;
        int gr1 = gr0 + 8;
#pragma unroll
        for (int ni = 0; ni < 4; ni++) {
            int col = n0 + wn + ni*8;
            if (MODE == 0) {
                int which = col / EMBED;
                int rem   = col - which * EMBED;
                int h     = rem / HDIM;
                int d0    = rem - h * HDIM + 2*q;
                float* dst = (which == 0) ? g_q : (which == 1) ? g_k : g_v;
                int b0i = gr0 >> 12, n0i = gr0 & 4095;
                int b1i = gr1 >> 12, n1i = gr1 & 4095;
                size_t i0 = (((size_t)(b0i*NHEAD + h))*SEQ + n0i)*HDIM + d0;
                size_t i1 = (((size_t)(b1i*NHEAD + h))*SEQ + n1i)*HDIM + d0;
                *(float2*)(dst + i0) = make_float2(f2tf(acc[mi][ni][0]), f2tf(acc[mi][ni][1]));
                *(float2*)(dst + i1) = make_float2(f2tf(acc[mi][ni][2]), f2tf(acc[mi][ni][3]));
            } else {
                size_t i0 = (size_t)gr0 * N + col + 2*q;
                size_t i1 = (size_t)gr1 * N + col + 2*q;
                *(float2*)(C + i0) = make_float2(acc[mi][ni][0], acc[mi][ni][1]);
                *(float2*)(C + i1) = make_float2(acc[mi][ni][2], acc[mi][ni][3]);
            }
        }
    }
}

// ---------------------------------------------------------------------------
// Flash attention v3. Grid (SEQ/256, B*H), 256 threads, 1 CTA/SM.
// BM=256, BN=64, 8 warps x 32 rows (2x fragment reuse). Q in smem (loaded
// once). P exchanged softmax->PV via quad shuffles (no smem, no extra barrier).
// 2-stage cp.async K/V, ONE barrier per iteration.
// ---------------------------------------------------------------------------
#define FPQ 100   // Q pitch: A-frag pattern (4g+q) conflict-free
#define FPK 100   // K pitch: S B-frag pattern (4g+q) conflict-free
#define FPV 104   // V pitch: PV B-frag pattern (8q+g) conflict-free

__global__ __launch_bounds__(256, 1) void flash3() {
    extern __shared__ float sm[];
    float* Qs = sm;                      // 256*FPQ
    float* Kb = Qs + 256*FPQ;            // 2 * 64*FPK
    float* Vb = Kb + 2*64*FPK;           // 2 * 64*FPV

    const int t = threadIdx.x;
    const int w = t >> 5, l = t & 31, g = l >> 2, q = l & 3;
    const int wm = w * 32;
    const int bh = blockIdx.y;
    const int q0 = blockIdx.x * 256;

    const float* Qg = g_q + (size_t)bh * SEQ * HDIM;
    const float* Kg = g_k + (size_t)bh * SEQ * HDIM;
    const float* Vg = g_v + (size_t)bh * SEQ * HDIM;

    const uint32_t qs_s = (uint32_t)__cvta_generic_to_shared(Qs);
    const uint32_t kb_s = (uint32_t)__cvta_generic_to_shared(Kb);
    const uint32_t vb_s = (uint32_t)__cvta_generic_to_shared(Vb);

    // Q tile 256x96 -> smem, once
#pragma unroll
    for (int j = 0; j < 24; j++) {
        int i = t + j*256;
        int r = i / 24, c = (i - r*24) * 4;
        cpasync16(qs_s + (uint32_t)((r*FPQ + c) * 4),
                  Qg + (size_t)(q0 + r) * HDIM + c);
    }
    asm volatile("cp.async.commit_group;\n" ::);

    auto load_tile = [&](int s, int kt) {
#pragma unroll
        for (int j = 0; j < 6; j++) {
            int i = t + j*256;
            int r = i / 24, c = (i - r*24) * 4;
            cpasync16(kb_s + (uint32_t)((s*64*FPK + r*FPK + c) * 4),
                      Kg + (size_t)(kt + r) * HDIM + c);
            cpasync16(vb_s + (uint32_t)((s*64*FPV + r*FPV + c) * 4),
                      Vg + (size_t)(kt + r) * HDIM + c);
        }
        asm volatile("cp.async.commit_group;\n" ::);
    };

    load_tile(0, 0);

    float of[2][12][4];
#pragma unroll
    for (int mi = 0; mi < 2; mi++)
#pragma unroll
        for (int ni = 0; ni < 12; ni++)
#pragma unroll
            for (int c = 0; c < 4; c++) of[mi][ni][c] = 0.f;
    // row states: r index 0..3 = rows wm+g, wm+8+g, wm+16+g, wm+24+g
    float mrow[4] = {-INFINITY, -INFINITY, -INFINITY, -INFINITY};
    float lrow[4] = {0.f, 0.f, 0.f, 0.f};

    for (int it = 0; it < SEQ/64; it++) {
        asm volatile("cp.async.wait_group 0;\n" ::);
        __syncthreads();                       // tiles visible; prev iter done
        if (it + 1 < SEQ/64) load_tile((it + 1) & 1, (it + 1) * 64);

        const float* Kc = Kb + (it & 1) * 64*FPK;
        const float* Vc = Vb + (it & 1) * 64*FPV;

        // ---- S = Q K^T : warp tile 32 x 64 ----
        float sacc[2][8][4];
#pragma unroll
        for (int mi = 0; mi < 2; mi++)
#pragma unroll
            for (int ni = 0; ni < 8; ni++)
#pragma unroll
                for (int c = 0; c < 4; c++) sacc[mi][ni][c] = 0.f;

#pragma unroll
        for (int kk = 0; kk < 12; kk++) {
            uint32_t qf[2][4];
#pragma unroll
            for (int mi = 0; mi < 2; mi++) {
                int r0 = wm + 16*mi + g;
                qf[mi][0] = __float_as_uint(Qs[r0*FPQ + 8*kk + q]);
                qf[mi][1] = __float_as_uint(Qs[(r0+8)*FPQ + 8*kk + q]);
                qf[mi][2] = __float_as_uint(Qs[r0*FPQ + 8*kk + q + 4]);
                qf[mi][3] = __float_as_uint(Qs[(r0+8)*FPQ + 8*kk + q + 4]);
            }
#pragma unroll
            for (int ni = 0; ni < 8; ni++) {
                uint32_t b0 = __float_as_uint(Kc[(8*ni + g)*FPK + 8*kk + q]);
                uint32_t b1 = __float_as_uint(Kc[(8*ni + g)*FPK + 8*kk + q + 4]);
                mma8(sacc[0][ni], qf[0][0], qf[0][1], qf[0][2], qf[0][3], b0, b1);
                mma8(sacc[1][ni], qf[1][0], qf[1][1], qf[1][2], qf[1][3], b0, b1);
            }
        }

        // ---- register online softmax over 4 rows ----
        float tm[4] = {-INFINITY, -INFINITY, -INFINITY, -INFINITY};
#pragma unroll
        for (int mi = 0; mi < 2; mi++)
#pragma unroll
            for (int ni = 0; ni < 8; ni++) {
                tm[2*mi]   = fmaxf(tm[2*mi],   fmaxf(sacc[mi][ni][0], sacc[mi][ni][1]));
                tm[2*mi+1] = fmaxf(tm[2*mi+1], fmaxf(sacc[mi][ni][2], sacc[mi][ni][3]));
            }
        float sc[4], base[4], ssum[4];
#pragma unroll
        for (int r = 0; r < 4; r++) {
            tm[r] = fmaxf(tm[r], __shfl_xor_sync(0xffffffffu, tm[r], 1));
            tm[r] = fmaxf(tm[r], __shfl_xor_sync(0xffffffffu, tm[r], 2));
            float mn = fmaxf(mrow[r], tm[r]);
            sc[r]   = exp2f((mrow[r] - mn) * C2EXP);
            base[r] = mn * C2EXP;
            mrow[r] = mn;
            ssum[r] = 0.f;
        }
#pragma unroll
        for (int mi = 0; mi < 2; mi++)
#pragma unroll
            for (int ni = 0; ni < 8; ni++) {
                float p0 = exp2f(fmaf(sacc[mi][ni][0], C2EXP, -base[2*mi]));
                float p1 = exp2f(fmaf(sacc[mi][ni][1], C2EXP, -base[2*mi]));
                float p2 = exp2f(fmaf(sacc[mi][ni][2], C2EXP, -base[2*mi+1]));
                float p3 = exp2f(fmaf(sacc[mi][ni][3], C2EXP, -base[2*mi+1]));
                sacc[mi][ni][0] = p0; sacc[mi][ni][1] = p1;
                sacc[mi][ni][2] = p2; sacc[mi][ni][3] = p3;
                ssum[2*mi]   += p0 + p1;
                ssum[2*mi+1] += p2 + p3;
            }
#pragma unroll
        for (int r = 0; r < 4; r++) {
            ssum[r] += __shfl_xor_sync(0xffffffffu, ssum[r], 1);
            ssum[r] += __shfl_xor_sync(0xffffffffu, ssum[r], 2);
            lrow[r] = lrow[r] * sc[r] + ssum[r];
        }
#pragma unroll
        for (int mi = 0; mi < 2; mi++)
#pragma unroll
            for (int ni = 0; ni < 12; ni++) {
                of[mi][ni][0] *= sc[2*mi];   of[mi][ni][1] *= sc[2*mi];
                of[mi][ni][2] *= sc[2*mi+1]; of[mi][ni][3] *= sc[2*mi+1];
            }

        // ---- O += P @ V : quad-shuffle P into A-fragments, no smem ----
#pragma unroll
        for (int kk2 = 0; kk2 < 8; kk2++) {
            uint32_t af[2][4];
#pragma unroll
            for (int mi = 0; mi < 2; mi++) {
                float p00 = sacc[mi][kk2][0], p01 = sacc[mi][kk2][1];
                float p10 = sacc[mi][kk2][2], p11 = sacc[mi][kk2][3];
                int s0 = q >> 1, s1 = (q >> 1) + 2;
                float x0 = __shfl_sync(0xffffffffu, p00, s0, 4);
                float x1 = __shfl_sync(0xffffffffu, p01, s0, 4);
                float x2 = __shfl_sync(0xffffffffu, p00, s1, 4);
                float x3 = __shfl_sync(0xffffffffu, p01, s1, 4);
                float y0 = __shfl_sync(0xffffffffu, p10, s0, 4);
                float y1 = __shfl_sync(0xffffffffu, p11, s0, 4);
                float y2 = __shfl_sync(0xffffffffu, p10, s1, 4);
                float y3 = __shfl_sync(0xffffffffu, p11, s1, 4);
                float a0 = (q & 1) ? x1 : x0;   // P[r0][8kk2+q]
                float a2 = (q & 1) ? x3 : x2;   // P[r0][8kk2+q+4]
                float a1 = (q & 1) ? y1 : y0;   // P[r0+8][8kk2+q]
                float a3 = (q & 1) ? y3 : y2;   // P[r0+8][8kk2+q+4]
                af[mi][0] = __float_as_uint(f2tf(a0));
                af[mi][1] = __float_as_uint(f2tf(a1));
                af[mi][2] = __float_as_uint(f2tf(a2));
                af[mi][3] = __float_as_uint(f2tf(a3));
            }
#pragma unroll
            for (int ni = 0; ni < 12; ni++) {
                uint32_t b0 = __float_as_uint(Vc[(8*kk2 + q)*FPV + 8*ni + g]);
                uint32_t b1 = __float_as_uint(Vc[(8*kk2 + 4 + q)*FPV + 8*ni + g]);
                mma8(of[0][ni], af[0][0], af[0][1], af[0][2], af[0][3], b0, b1);
                mma8(of[1][ni], af[1][0], af[1][1], af[1][2], af[1][3], b0, b1);
            }
        }
    }

    // epilogue: normalize + write [B, N, H*D]
    const int b = bh >> 3, h = bh & 7;
    float inv[4];
#pragma unroll
    for (int r = 0; r < 4; r++) inv[r] = 1.f / lrow[r];
#pragma unroll
    for (int mi = 0; mi < 2; mi++) {
        size_t r0 = ((size_t)(b*SEQ + q0 + wm + 16*mi + g)) * EMBED + h*HDIM;
        size_t r1 = r0 + (size_t)8 * EMBED;
#pragma unroll
        for (int ni = 0; ni < 12; ni++) {
            *(float2*)(g_att + r0 + 8*ni + 2*q) =
                make_float2(of[mi][ni][0]*inv[2*mi], of[mi][ni][1]*inv[2*mi]);
            *(float2*)(g_att + r1 + 8*ni + 2*q) =
                make_float2(of[mi][ni][2]*inv[2*mi+1], of[mi][ni][3]*inv[2*mi+1]);
        }
    }
}

static const int FLASH_SMEM = (256*FPQ + 2*64*FPK + 2*64*FPV) * (int)sizeof(float); // 206848

extern "C" void kernel_launch(void* const* d_in, const int* in_sizes, int n_in,
                              void* d_out, int out_size) {
    const float* x      = (const float*)d_in[0];   // [2,4096,768]
    const float* w_qkv  = (const float*)d_in[1];   // [2304,768]
    const float* w_proj = (const float*)d_in[2];   // [768,768]
    float* out = (float*)d_out;                    // [2,4096,768]

    static bool attr_set = false;
    if (!attr_set) {
        cudaFuncSetAttribute(flash3, cudaFuncAttributeMaxDynamicSharedMemorySize,
                             FLASH_SMEM);
        attr_set = true;
    }

    tgemm<0><<<dim3(QKV_N/128, MTOT/128), 256>>>(x, w_qkv, nullptr,
                                                 MTOT, QKV_N, EMBED);
    flash3<<<dim3(SEQ/256, BATCH*NHEAD), 256, FLASH_SMEM>>>();
    tgemm<1><<<dim3(EMBED/128, MTOT/128), 256>>>(nullptr, w_proj, out,
                                                 MTOT, EMBED, EMBED);
}

// round 9
// speedup vs baseline: 8.8175x; 2.0028x over previous
#include <cuda_runtime.h>
#include <cuda_fp16.h>
#include <math.h>
#include <stdint.h>

#define BATCH 2
#define SEQ   4096
#define EMBED 768
#define NHEAD 8
#define HDIM  96
#define MTOT  (BATCH*SEQ)          // 8192
#define QKV_N (3*EMBED)            // 2304
#define C2EXP  0.14724446f         // 96^-0.5 * log2(e)

// ------------------------- device scratch (fp16) -------------------------
__device__ __align__(16) __half g_q[(size_t)BATCH*NHEAD*SEQ*HDIM];   // [B,H,N,D]
__device__ __align__(16) __half g_k[(size_t)BATCH*NHEAD*SEQ*HDIM];   // [B,H,N,D]
__device__ __align__(16) __half g_v[(size_t)BATCH*NHEAD*SEQ*HDIM];   // [B,H,D,N] (transposed)
__device__ __align__(16) __half g_xh[(size_t)MTOT*EMBED];
__device__ __align__(16) __half g_wqkvh[(size_t)QKV_N*EMBED];
__device__ __align__(16) __half g_wprojh[(size_t)EMBED*EMBED];
__device__ __align__(16) __half g_atth[(size_t)MTOT*EMBED];

// ------------------------- helpers -------------------------
__device__ __forceinline__ void mma16(float* c, uint32_t a0, uint32_t a1,
                                      uint32_t a2, uint32_t a3,
                                      uint32_t b0, uint32_t b1) {
    asm volatile(
        "mma.sync.aligned.m16n8k16.row.col.f32.f16.f16.f32 "
        "{%0,%1,%2,%3}, {%4,%5,%6,%7}, {%8,%9}, {%0,%1,%2,%3};"
        : "+f"(c[0]), "+f"(c[1]), "+f"(c[2]), "+f"(c[3])
        : "r"(a0), "r"(a1), "r"(a2), "r"(a3), "r"(b0), "r"(b1));
}

__device__ __forceinline__ void cpasync16(uint32_t dst, const void* src) {
    asm volatile("cp.async.cg.shared.global [%0], [%1], 16;\n"
                 :: "r"(dst), "l"(src));
}

__device__ __forceinline__ uint32_t s2u(const void* p) {
    uint32_t a;
    asm("{ .reg .u64 t; cvta.to.shared.u64 t, %1; cvt.u32.u64 %0, t; }"
        : "=r"(a) : "l"(p));
    return a;
}

__device__ __forceinline__ uint32_t h2u(__half2 h) {
    return *(uint32_t*)&h;
}

// ------------------------- fp32 -> fp16 convert -------------------------
__global__ void cvt_half(const float* __restrict__ s, __half* __restrict__ d, int n2) {
    for (int i = blockIdx.x * blockDim.x + threadIdx.x; i < n2;
         i += gridDim.x * blockDim.x) {
        float2 v = ((const float2*)s)[i];
        ((__half2*)d)[i] = __floats2half2_rn(v.x, v.y);
    }
}

// ---------------------------------------------------------------------------
// fp16 GEMM: C = A @ B^T (A [M,K] rm, B [N,K] rm), m16n8k16, f32 accum.
// 128x128 CTA tile, BK=64, cp.async 2-stage, 8 warps of 64x32, 2 CTAs/SM.
// MODE 0: A=g_xh, B=g_wqkvh -> scatter fp16 to g_q/g_k (n-major) and g_v (d-major).
// MODE 1: A=g_atth, B=g_wprojh -> write float Cout.
// ---------------------------------------------------------------------------
#define HGP 72                    // smem pitch in halves (word-stride 36 == 4 mod 8)
#define HST (128*HGP*2)           // bytes per matrix per stage (18432)
#define HGEMM_SMEM (4*HST)        // 73728

template<int MODE>
__global__ __launch_bounds__(256, 2) void hgemm(float* __restrict__ Cout) {
    extern __shared__ char dynsm[];
    const uint32_t sb = s2u(dynsm);
    const int t = threadIdx.x, w = t >> 5, l = t & 31, g = l >> 2, q = l & 3;
    const int wm = (w >> 2) * 64, wn = (w & 3) * 32;
    const int m0 = blockIdx.y * 128, n0 = blockIdx.x * 128;
    const int K = EMBED;

    const __half* A = (MODE == 0) ? g_xh : g_atth;
    const __half* B = (MODE == 0) ? g_wqkvh : g_wprojh;

    auto load_chunk = [&](int s, int kt) {
        uint32_t base = sb + s * (2 * HST);
#pragma unroll
        for (int j = 0; j < 8; j++) {
            int idx = t + j * 256;
            int tile = idx >> 10, rem = idx & 1023;
            int r = rem >> 3, cb = rem & 7;
            const __half* src = tile ? (B + (size_t)(n0 + r) * K)
                                     : (A + (size_t)(m0 + r) * K);
            cpasync16(base + tile * HST + (uint32_t)((r * HGP + cb * 8) * 2),
                      src + kt + cb * 8);
        }
        asm volatile("cp.async.commit_group;\n" ::);
    };

    float acc[4][4][4];
#pragma unroll
    for (int mi = 0; mi < 4; mi++)
#pragma unroll
        for (int ni = 0; ni < 4; ni++)
#pragma unroll
            for (int c = 0; c < 4; c++) acc[mi][ni][c] = 0.f;

    load_chunk(0, 0);

    for (int c = 0; c < 12; c++) {
        if (c + 1 < 12) {
            load_chunk((c + 1) & 1, (c + 1) * 64);
            asm volatile("cp.async.wait_group 1;\n" ::);
        } else {
            asm volatile("cp.async.wait_group 0;\n" ::);
        }
        __syncthreads();

        const __half* As = (const __half*)(dynsm + (c & 1) * (2 * HST));
        const __half* Bs = (const __half*)(dynsm + (c & 1) * (2 * HST) + HST);

#pragma unroll
        for (int ks = 0; ks < 4; ks++) {
            uint32_t af[4][4], bf[4][2];
#pragma unroll
            for (int mi = 0; mi < 4; mi++) {
                int r0 = wm + 16 * mi + g;
                af[mi][0] = *(const uint32_t*)&As[r0 * HGP + 16 * ks + 2 * q];
                af[mi][1] = *(const uint32_t*)&As[(r0 + 8) * HGP + 16 * ks + 2 * q];
                af[mi][2] = *(const uint32_t*)&As[r0 * HGP + 16 * ks + 2 * q + 8];
                af[mi][3] = *(const uint32_t*)&As[(r0 + 8) * HGP + 16 * ks + 2 * q + 8];
            }
#pragma unroll
            for (int ni = 0; ni < 4; ni++) {
                int r0 = wn + 8 * ni + g;
                bf[ni][0] = *(const uint32_t*)&Bs[r0 * HGP + 16 * ks + 2 * q];
                bf[ni][1] = *(const uint32_t*)&Bs[r0 * HGP + 16 * ks + 2 * q + 8];
            }
#pragma unroll
            for (int mi = 0; mi < 4; mi++)
#pragma unroll
                for (int ni = 0; ni < 4; ni++)
                    mma16(acc[mi][ni], af[mi][0], af[mi][1], af[mi][2], af[mi][3],
                          bf[ni][0], bf[ni][1]);
        }
        __syncthreads();
    }

#pragma unroll
    for (int mi = 0; mi < 4; mi++) {
        int gr0 = m0 + wm + 16 * mi + g;
        int gr1 = gr0 + 8;
#pragma unroll
        for (int ni = 0; ni < 4; ni++) {
            int colb = n0 + wn + 8 * ni;
            if (MODE == 0) {
                int which = colb / EMBED;
                int rem = colb - which * EMBED;
                int h = rem / HDIM;
                int d0 = rem - h * HDIM + 2 * q;
                int b0i = gr0 >> 12, n0i = gr0 & 4095;
                int b1i = gr1 >> 12, n1i = gr1 & 4095;
                if (which < 2) {
                    __half* dst = which ? g_k : g_q;
                    size_t i0 = (((size_t)(b0i * NHEAD + h)) * SEQ + n0i) * HDIM + d0;
                    size_t i1 = (((size_t)(b1i * NHEAD + h)) * SEQ + n1i) * HDIM + d0;
                    *(__half2*)(dst + i0) = __floats2half2_rn(acc[mi][ni][0], acc[mi][ni][1]);
                    *(__half2*)(dst + i1) = __floats2half2_rn(acc[mi][ni][2], acc[mi][ni][3]);
                } else {
                    // V transposed: [B,H,D,N]
                    size_t base0 = (((size_t)(b0i * NHEAD + h)) * HDIM + d0) * SEQ;
                    size_t base1 = (((size_t)(b1i * NHEAD + h)) * HDIM + d0) * SEQ;
                    g_v[base0 + n0i]       = __float2half(acc[mi][ni][0]);
                    g_v[base0 + SEQ + n0i] = __float2half(acc[mi][ni][1]);
                    g_v[base1 + n1i]       = __float2half(acc[mi][ni][2]);
                    g_v[base1 + SEQ + n1i] = __float2half(acc[mi][ni][3]);
                }
            } else {
                size_t i0 = (size_t)gr0 * EMBED + colb + 2 * q;
                size_t i1 = (size_t)gr1 * EMBED + colb + 2 * q;
                *(float2*)(Cout + i0) = make_float2(acc[mi][ni][0], acc[mi][ni][1]);
                *(float2*)(Cout + i1) = make_float2(acc[mi][ni][2], acc[mi][ni][3]);
            }
        }
    }
}

// ---------------------------------------------------------------------------
// Flash attention, fp16 m16n8k16. Grid (SEQ/256, B*H), 256 threads, 1 CTA/SM.
// BM=256, BN=64, 8 warps x 32 rows. Q in smem once. P handoff is pure
// register packing (k16 C-layout == A-layout). V d-major for half2 B-frags.
// ---------------------------------------------------------------------------
#define FQP 104   // word-stride 52 == 20 mod 32: g*20+q bijective
#define FKP 104
#define FVP 72    // word-stride 36 == 4 mod 32:  g*4+q bijective

__global__ __launch_bounds__(256, 1) void flash_h() {
    extern __shared__ char dynsm[];
    __half* Qs = (__half*)dynsm;                 // 256*FQP
    __half* Kb = Qs + 256*FQP;                   // 2 * 64*FKP
    __half* Vb = Kb + 2*64*FKP;                  // 2 * 96*FVP

    const int t = threadIdx.x;
    const int w = t >> 5, l = t & 31, g = l >> 2, q = l & 3;
    const int wm = w * 32;
    const int bh = blockIdx.y;
    const int q0 = blockIdx.x * 256;

    const __half* Qg = g_q + (size_t)bh * SEQ * HDIM;
    const __half* Kg = g_k + (size_t)bh * SEQ * HDIM;
    const __half* Vg = g_v + (size_t)bh * HDIM * SEQ;   // [D,N]

    const uint32_t qs_s = s2u(Qs);
    const uint32_t kb_s = s2u(Kb);
    const uint32_t vb_s = s2u(Vb);

    // Q tile: 256 rows x 96 halves = 3072 16B chunks
#pragma unroll
    for (int j = 0; j < 12; j++) {
        int idx = t + j * 256;
        int r = idx / 12, cb = idx % 12;
        cpasync16(qs_s + (uint32_t)((r * FQP + cb * 8) * 2),
                  Qg + (size_t)(q0 + r) * HDIM + cb * 8);
    }
    asm volatile("cp.async.commit_group;\n" ::);

    auto load_tile = [&](int s, int kt) {
#pragma unroll
        for (int j = 0; j < 3; j++) {           // K: 64 rows x 12 chunks
            int idx = t + j * 256;
            int r = idx / 12, cb = idx % 12;
            cpasync16(kb_s + (uint32_t)((s * 64 * FKP + r * FKP + cb * 8) * 2),
                      Kg + (size_t)(kt + r) * HDIM + cb * 8);
        }
#pragma unroll
        for (int j = 0; j < 3; j++) {           // V: 96 d-rows x 8 chunks of seq
            int idx = t + j * 256;
            int r = idx >> 3, cb = idx & 7;
            cpasync16(vb_s + (uint32_t)((s * 96 * FVP + r * FVP + cb * 8) * 2),
                      Vg + (size_t)r * SEQ + kt + cb * 8);
        }
        asm volatile("cp.async.commit_group;\n" ::);
    };

    load_tile(0, 0);

    float of[2][12][4];
#pragma unroll
    for (int mi = 0; mi < 2; mi++)
#pragma unroll
        for (int ni = 0; ni < 12; ni++)
#pragma unroll
            for (int c = 0; c < 4; c++) of[mi][ni][c] = 0.f;
    float mrow[4] = {-INFINITY, -INFINITY, -INFINITY, -INFINITY};
    float lrow[4] = {0.f, 0.f, 0.f, 0.f};

    for (int it = 0; it < SEQ/64; it++) {
        asm volatile("cp.async.wait_group 0;\n" ::);
        __syncthreads();
        if (it + 1 < SEQ/64) load_tile((it + 1) & 1, (it + 1) * 64);

        const __half* Kc = Kb + (it & 1) * 64*FKP;
        const __half* Vc = Vb + (it & 1) * 96*FVP;

        // ---- S = Q K^T : warp tile 32 x 64, 6 k16-steps ----
        float sacc[2][8][4];
#pragma unroll
        for (int mi = 0; mi < 2; mi++)
#pragma unroll
            for (int ni = 0; ni < 8; ni++)
#pragma unroll
                for (int c = 0; c < 4; c++) sacc[mi][ni][c] = 0.f;

#pragma unroll
        for (int kk = 0; kk < 6; kk++) {
            uint32_t qf[2][4];
#pragma unroll
            for (int mi = 0; mi < 2; mi++) {
                int r0 = wm + 16 * mi + g;
                qf[mi][0] = *(const uint32_t*)&Qs[r0 * FQP + 16 * kk + 2 * q];
                qf[mi][1] = *(const uint32_t*)&Qs[(r0 + 8) * FQP + 16 * kk + 2 * q];
                qf[mi][2] = *(const uint32_t*)&Qs[r0 * FQP + 16 * kk + 2 * q + 8];
                qf[mi][3] = *(const uint32_t*)&Qs[(r0 + 8) * FQP + 16 * kk + 2 * q + 8];
            }
#pragma unroll
            for (int ni = 0; ni < 8; ni++) {
                uint32_t b0 = *(const uint32_t*)&Kc[(8 * ni + g) * FKP + 16 * kk + 2 * q];
                uint32_t b1 = *(const uint32_t*)&Kc[(8 * ni + g) * FKP + 16 * kk + 2 * q + 8];
                mma16(sacc[0][ni], qf[0][0], qf[0][1], qf[0][2], qf[0][3], b0, b1);
                mma16(sacc[1][ni], qf[1][0], qf[1][1], qf[1][2], qf[1][3], b0, b1);
            }
        }

        // ---- register online softmax (4 rows: wm+g, wm+8+g, wm+16+g, wm+24+g) ----
        float tm[4] = {-INFINITY, -INFINITY, -INFINITY, -INFINITY};
#pragma unroll
        for (int mi = 0; mi < 2; mi++)
#pragma unroll
            for (int ni = 0; ni < 8; ni++) {
                tm[2*mi]   = fmaxf(tm[2*mi],   fmaxf(sacc[mi][ni][0], sacc[mi][ni][1]));
                tm[2*mi+1] = fmaxf(tm[2*mi+1], fmaxf(sacc[mi][ni][2], sacc[mi][ni][3]));
            }
        float sc[4], base[4], ssum[4];
#pragma unroll
        for (int r = 0; r < 4; r++) {
            tm[r] = fmaxf(tm[r], __shfl_xor_sync(0xffffffffu, tm[r], 1));
            tm[r] = fmaxf(tm[r], __shfl_xor_sync(0xffffffffu, tm[r], 2));
            float mn = fmaxf(mrow[r], tm[r]);
            sc[r]   = exp2f((mrow[r] - mn) * C2EXP);
            base[r] = mn * C2EXP;
            mrow[r] = mn;
            ssum[r] = 0.f;
        }
#pragma unroll
        for (int mi = 0; mi < 2; mi++)
#pragma unroll
            for (int ni = 0; ni < 8; ni++) {
                float p0 = exp2f(fmaf(sacc[mi][ni][0], C2EXP, -base[2*mi]));
                float p1 = exp2f(fmaf(sacc[mi][ni][1], C2EXP, -base[2*mi]));
                float p2 = exp2f(fmaf(sacc[mi][ni][2], C2EXP, -base[2*mi+1]));
                float p3 = exp2f(fmaf(sacc[mi][ni][3], C2EXP, -base[2*mi+1]));
                sacc[mi][ni][0] = p0; sacc[mi][ni][1] = p1;
                sacc[mi][ni][2] = p2; sacc[mi][ni][3] = p3;
                ssum[2*mi]   += p0 + p1;
                ssum[2*mi+1] += p2 + p3;
            }
#pragma unroll
        for (int r = 0; r < 4; r++) {
            ssum[r] += __shfl_xor_sync(0xffffffffu, ssum[r], 1);
            ssum[r] += __shfl_xor_sync(0xffffffffu, ssum[r], 2);
            lrow[r] = lrow[r] * sc[r] + ssum[r];
        }
#pragma unroll
        for (int mi = 0; mi < 2; mi++)
#pragma unroll
            for (int ni = 0; ni < 12; ni++) {
                of[mi][ni][0] *= sc[2*mi];   of[mi][ni][1] *= sc[2*mi];
                of[mi][ni][2] *= sc[2*mi+1]; of[mi][ni][3] *= sc[2*mi+1];
            }

        // ---- O += P @ V : C-layout == A-layout, pure register pack ----
#pragma unroll
        for (int kk2 = 0; kk2 < 4; kk2++) {
            uint32_t af[2][4];
#pragma unroll
            for (int mi = 0; mi < 2; mi++) {
                af[mi][0] = h2u(__floats2half2_rn(sacc[mi][2*kk2][0],   sacc[mi][2*kk2][1]));
                af[mi][1] = h2u(__floats2half2_rn(sacc[mi][2*kk2][2],   sacc[mi][2*kk2][3]));
                af[mi][2] = h2u(__floats2half2_rn(sacc[mi][2*kk2+1][0], sacc[mi][2*kk2+1][1]));
                af[mi][3] = h2u(__floats2half2_rn(sacc[mi][2*kk2+1][2], sacc[mi][2*kk2+1][3]));
            }
#pragma unroll
            for (int ni = 0; ni < 12; ni++) {
                uint32_t b0 = *(const uint32_t*)&Vc[(8 * ni + g) * FVP + 16 * kk2 + 2 * q];
                uint32_t b1 = *(const uint32_t*)&Vc[(8 * ni + g) * FVP + 16 * kk2 + 2 * q + 8];
                mma16(of[0][ni], af[0][0], af[0][1], af[0][2], af[0][3], b0, b1);
                mma16(of[1][ni], af[1][0], af[1][1], af[1][2], af[1][3], b0, b1);
            }
        }
    }

    // epilogue: normalize + write fp16 att [B*N, C]
    const int b = bh >> 3, h = bh & 7;
    float inv[4];
#pragma unroll
    for (int r = 0; r < 4; r++) inv[r] = 1.f / lrow[r];
#pragma unroll
    for (int mi = 0; mi < 2; mi++) {
        size_t r0 = ((size_t)(b*SEQ + q0 + wm + 16*mi + g)) * EMBED + h*HDIM;
        size_t r1 = r0 + (size_t)8 * EMBED;
#pragma unroll
        for (int ni = 0; ni < 12; ni++) {
            *(__half2*)(g_atth + r0 + 8*ni + 2*q) =
                __floats2half2_rn(of[mi][ni][0]*inv[2*mi], of[mi][ni][1]*inv[2*mi]);
            *(__half2*)(g_atth + r1 + 8*ni + 2*q) =
                __floats2half2_rn(of[mi][ni][2]*inv[2*mi+1], of[mi][ni][3]*inv[2*mi+1]);
        }
    }
}

static const int FLASH_SMEM = (256*FQP + 2*64*FKP + 2*96*FVP) * 2;  // 107520

extern "C" void kernel_launch(void* const* d_in, const int* in_sizes, int n_in,
                              void* d_out, int out_size) {
    const float* x      = (const float*)d_in[0];
    const float* w_qkv  = (const float*)d_in[1];
    const float* w_proj = (const float*)d_in[2];
    float* out = (float*)d_out;

    static bool attr_set = false;
    if (!attr_set) {
        cudaFuncSetAttribute(flash_h, cudaFuncAttributeMaxDynamicSharedMemorySize,
                             FLASH_SMEM);
        cudaFuncSetAttribute(hgemm<0>, cudaFuncAttributeMaxDynamicSharedMemorySize,
                             HGEMM_SMEM);
        cudaFuncSetAttribute(hgemm<1>, cudaFuncAttributeMaxDynamicSharedMemorySize,
                             HGEMM_SMEM);
        attr_set = true;
    }

    __half *xh, *wqh, *wph;
    cudaGetSymbolAddress((void**)&xh,  g_xh);
    cudaGetSymbolAddress((void**)&wqh, g_wqkvh);
    cudaGetSymbolAddress((void**)&wph, g_wprojh);

    cvt_half<<<1024, 256>>>(x, xh, MTOT*EMBED/2);
    cvt_half<<<512, 256>>>(w_qkv, wqh, QKV_N*EMBED/2);
    cvt_half<<<256, 256>>>(w_proj, wph, EMBED*EMBED/2);

    hgemm<0><<<dim3(QKV_N/128, MTOT/128), 256, HGEMM_SMEM>>>(nullptr);
    flash_h<<<dim3(SEQ/256, BATCH*NHEAD), 256, FLASH_SMEM>>>();
    hgemm<1><<<dim3(EMBED/128, MTOT/128), 256, HGEMM_SMEM>>>(out);
}